// round 1
// baseline (speedup 1.0000x reference)
#include <cuda_runtime.h>
#include <math.h>

#define EPSF 1e-7f
#define MAX_TANHF (1.0f - 1e-6f)

constexpr int F = 128;
constexpr int NMAX = 8192;

// Scratch (no allocation allowed anywhere)
__device__ float g_T [NMAX * F];      // log0(x)
__device__ float g_U [NMAX * F];      // T @ embed
__device__ float g_V [NMAX * F];      // log0(h)
__device__ float g_NT[NMAX * F];      // adj @ V
__device__ float g_C [NMAX * 2 * F];  // log0([x ; neigh])
__device__ float g_U2[NMAX * F];      // C @ layer

// ---------------------------------------------------------------------------
// Block-wide sum over 128 threads (4 warps)
// ---------------------------------------------------------------------------
__device__ __forceinline__ float blk_sum128(float v) {
    __shared__ float s[4];
    const unsigned m = 0xffffffffu;
    v += __shfl_down_sync(m, v, 16);
    v += __shfl_down_sync(m, v, 8);
    v += __shfl_down_sync(m, v, 4);
    v += __shfl_down_sync(m, v, 2);
    v += __shfl_down_sync(m, v, 1);
    __syncthreads();  // protect s[] from previous call's readers
    if ((threadIdx.x & 31) == 0) s[threadIdx.x >> 5] = v;
    __syncthreads();
    return s[0] + s[1] + s[2] + s[3];
}

// ---------------------------------------------------------------------------
// K1: T = log0(x)   (rowwise, one block of 128 threads per row)
// ---------------------------------------------------------------------------
__global__ void k_row_log0(const float* __restrict__ x) {
    int i = blockIdx.x, t = threadIdx.x;
    float v = x[(size_t)i * F + t];
    float n2 = blk_sum128(v * v);
    float n = fmaxf(sqrtf(n2), EPSF);
    float tc = fminf(n, MAX_TANHF);
    g_T[(size_t)i * F + t] = (atanhf(tc) / n) * v;
}

// ---------------------------------------------------------------------------
// Tiled fp32 GEMM: C[M,128] = A[M,K] @ B[K,128]. B fully in smem.
// 256 threads, 64-row tile, each thread: 8 rows x 4 cols.
// ---------------------------------------------------------------------------
template <int K>
__global__ void k_gemm(const float* __restrict__ A, const float* __restrict__ B,
                       float* __restrict__ C) {
    extern __shared__ float sm[];
    float* Bs = sm;            // K * 128
    float* As = sm + K * 128;  // 64 * K
    int tid = threadIdx.x;
    int row0 = blockIdx.x * 64;

    const float4* B4 = (const float4*)B;
    float4*       Bs4 = (float4*)Bs;
    for (int i = tid; i < K * 128 / 4; i += 256) Bs4[i] = B4[i];

    const float4* A4 = (const float4*)(A + (size_t)row0 * K);
    float4*       As4 = (float4*)As;
    for (int i = tid; i < 64 * K / 4; i += 256) As4[i] = A4[i];
    __syncthreads();

    int c4 = (tid & 31) * 4;
    int r8 = (tid >> 5) * 8;

    float4 acc[8];
#pragma unroll
    for (int r = 0; r < 8; r++) acc[r] = make_float4(0.f, 0.f, 0.f, 0.f);

#pragma unroll 4
    for (int k = 0; k < K; k++) {
        float4 b = *(const float4*)(Bs + k * 128 + c4);
#pragma unroll
        for (int r = 0; r < 8; r++) {
            float a = As[(r8 + r) * K + k];
            acc[r].x += a * b.x;
            acc[r].y += a * b.y;
            acc[r].z += a * b.z;
            acc[r].w += a * b.w;
        }
    }
#pragma unroll
    for (int r = 0; r < 8; r++)
        *(float4*)(C + (size_t)(row0 + r8 + r) * 128 + c4) = acc[r];
}

// ---------------------------------------------------------------------------
// K3: h = h_add(exp0(U), embed_bias);  V = log0(h)
// ---------------------------------------------------------------------------
__global__ void k_row_mid(const float* __restrict__ ebias) {
    int i = blockIdx.x, t = threadIdx.x;
    float u = g_U[(size_t)i * F + t];
    float ne2 = blk_sum128(u * u);
    float ne = fmaxf(sqrtf(ne2), EPSF);
    float h = (tanhf(ne) / ne) * u;

    float b = ebias[t];
    float xy = blk_sum128(h * b);
    float x2 = blk_sum128(h * h);
    float y2 = blk_sum128(b * b);

    float num = (1.f + 2.f * xy + y2) * h + (1.f - x2) * b;
    float den = fmaxf(1.f + 2.f * xy + x2 * y2, EPSF);
    float r = num / den;

    float nr2 = blk_sum128(r * r);
    float nr = fmaxf(sqrtf(nr2), EPSF);
    float tc = fminf(nr, MAX_TANHF);
    g_V[(size_t)i * F + t] = (atanhf(tc) / nr) * r;
}

// ---------------------------------------------------------------------------
// K4: NT = adj @ V, sparse-aware. One warp per output row.
// ---------------------------------------------------------------------------
__global__ void k_spmm(const float* __restrict__ adj, int N) {
    int warp = (blockIdx.x * blockDim.x + threadIdx.x) >> 5;
    int lane = threadIdx.x & 31;
    if (warp >= N) return;

    const float4* V4 = (const float4*)g_V;
    const float4* arow = (const float4*)(adj + (size_t)warp * N);
    float4 acc = make_float4(0.f, 0.f, 0.f, 0.f);

    int nq = N / 4;  // row length in float4
    for (int jb = 0; jb < nq; jb += 32) {
        float4 a = arow[jb + lane];
#pragma unroll
        for (int c = 0; c < 4; c++) {
            float av = (c == 0) ? a.x : (c == 1) ? a.y : (c == 2) ? a.z : a.w;
            unsigned m = __ballot_sync(0xffffffffu, av != 0.0f);
            while (m) {
                int b = __ffs(m) - 1;
                m &= m - 1;
                float aval = __shfl_sync(0xffffffffu, av, b);
                int j = (jb + b) * 4 + c;
                float4 v = V4[(size_t)j * 32 + lane];
                acc.x += aval * v.x;
                acc.y += aval * v.y;
                acc.z += aval * v.z;
                acc.w += aval * v.w;
            }
        }
    }
    ((float4*)g_NT)[(size_t)warp * 32 + lane] = acc;
}

// ---------------------------------------------------------------------------
// K5: neigh = exp0(NT);  C = log0([x ; neigh])  (norm over 256 dims)
// ---------------------------------------------------------------------------
__global__ void k_row_concat(const float* __restrict__ x) {
    int i = blockIdx.x, t = threadIdx.x;
    float xv = x[(size_t)i * F + t];
    float nt = g_NT[(size_t)i * F + t];

    float nn2 = blk_sum128(nt * nt);
    float nn = fmaxf(sqrtf(nn2), EPSF);
    float ng = (tanhf(nn) / nn) * nt;  // neigh component

    float nx2 = blk_sum128(xv * xv);
    float ng2 = blk_sum128(ng * ng);

    float nc = fmaxf(sqrtf(nx2 + ng2), EPSF);
    float tc = fminf(nc, MAX_TANHF);
    float s = atanhf(tc) / nc;

    g_C[(size_t)i * 2 * F + t]     = s * xv;
    g_C[(size_t)i * 2 * F + F + t] = s * ng;
}

// ---------------------------------------------------------------------------
// K7: out = h_add(exp0(U2), layer_bias)
// ---------------------------------------------------------------------------
__global__ void k_row_out(const float* __restrict__ lbias, float* __restrict__ out) {
    int i = blockIdx.x, t = threadIdx.x;
    float u = g_U2[(size_t)i * F + t];
    float ne2 = blk_sum128(u * u);
    float ne = fmaxf(sqrtf(ne2), EPSF);
    float h = (tanhf(ne) / ne) * u;

    float b = lbias[t];
    float xy = blk_sum128(h * b);
    float x2 = blk_sum128(h * h);
    float y2 = blk_sum128(b * b);

    float num = (1.f + 2.f * xy + y2) * h + (1.f - x2) * b;
    float den = fmaxf(1.f + 2.f * xy + x2 * y2, EPSF);
    out[(size_t)i * F + t] = num / den;
}

// ---------------------------------------------------------------------------
extern "C" void kernel_launch(void* const* d_in, const int* in_sizes, int n_in,
                              void* d_out, int out_size) {
    const float* x     = (const float*)d_in[0];
    const float* adj   = (const float*)d_in[1];
    const float* embed = (const float*)d_in[2];
    const float* layer = (const float*)d_in[3];
    const float* ebias = (const float*)d_in[4];
    const float* lbias = (const float*)d_in[5];
    float* out = (float*)d_out;

    int N = in_sizes[0] / F;  // 8192

    float *pT, *pU, *pC, *pU2;
    cudaGetSymbolAddress((void**)&pT, g_T);
    cudaGetSymbolAddress((void**)&pU, g_U);
    cudaGetSymbolAddress((void**)&pC, g_C);
    cudaGetSymbolAddress((void**)&pU2, g_U2);

    const int SMEM128 = (128 * 128 + 64 * 128) * 4;  //  96 KB
    const int SMEM256 = (256 * 128 + 64 * 256) * 4;  // 192 KB
    cudaFuncSetAttribute(k_gemm<128>, cudaFuncAttributeMaxDynamicSharedMemorySize, SMEM128);
    cudaFuncSetAttribute(k_gemm<256>, cudaFuncAttributeMaxDynamicSharedMemorySize, SMEM256);

    k_row_log0<<<N, 128>>>(x);
    k_gemm<128><<<N / 64, 256, SMEM128>>>(pT, embed, pU);
    k_row_mid<<<N, 128>>>(ebias);
    k_spmm<<<N / 8, 256>>>(adj, N);
    k_row_concat<<<N, 128>>>(x);
    k_gemm<256><<<N / 64, 256, SMEM256>>>(pC, layer, pU2);
    k_row_out<<<N, 128>>>(lbias, out);
}

// round 2
// speedup vs baseline: 1.3960x; 1.3960x over previous
#include <cuda_runtime.h>
#include <math.h>

#define EPSF 1e-7f
#define MAX_TANHF (1.0f - 1e-6f)

constexpr int F = 128;
constexpr int NMAX = 8192;

// Scratch (no allocation allowed anywhere)
__device__ float g_V [NMAX * F];      // log0(h)  (output of stage 1)
__device__ float g_C [NMAX * 2 * F];  // log0([x ; neigh]) (output of stage 2)

__device__ __forceinline__ float warp_sum(float v) {
    v += __shfl_xor_sync(0xffffffffu, v, 16);
    v += __shfl_xor_sync(0xffffffffu, v, 8);
    v += __shfl_xor_sync(0xffffffffu, v, 4);
    v += __shfl_xor_sync(0xffffffffu, v, 2);
    v += __shfl_xor_sync(0xffffffffu, v, 1);
    return v;
}

__device__ __forceinline__ float dot4(float4 a, float4 b) {
    return a.x * b.x + a.y * b.y + a.z * b.z + a.w * b.w;
}

// ---------------------------------------------------------------------------
// Stage 1: V = log0( h_add( exp0( log0(x) @ embed ), ebias ) )
// 256 threads, 64-row tile. Each thread: 8 rows x 4 cols; each row of the
// output tile is owned by exactly one warp -> warp-shuffle row reductions.
// ---------------------------------------------------------------------------
__global__ void k_gemm128_fused(const float* __restrict__ x,
                                const float* __restrict__ B,
                                const float* __restrict__ ebias,
                                float* __restrict__ V) {
    extern __shared__ float sm[];
    float* Bs = sm;                // 128*128
    float* As = sm + 128 * 128;    // 64*128
    int tid = threadIdx.x;
    int lane = tid & 31, w = tid >> 5;
    int row0 = blockIdx.x * 64;

    const float4* B4 = (const float4*)B;
    float4* Bs4 = (float4*)Bs;
    for (int i = tid; i < 128 * 128 / 4; i += 256) Bs4[i] = B4[i];

    const float4* X4 = (const float4*)(x + (size_t)row0 * 128);
    float4* As4 = (float4*)As;
    for (int i = tid; i < 64 * 128 / 4; i += 256) As4[i] = X4[i];
    __syncthreads();

    // prologue: log0 per row, in smem (each warp owns 8 rows)
#pragma unroll
    for (int r = 0; r < 8; r++) {
        int row = w * 8 + r;
        float4 a = As4[row * 32 + lane];
        float s2 = warp_sum(dot4(a, a));
        float n = fmaxf(sqrtf(s2), EPSF);
        float sc = atanhf(fminf(n, MAX_TANHF)) / n;
        a.x *= sc; a.y *= sc; a.z *= sc; a.w *= sc;
        As4[row * 32 + lane] = a;
    }
    __syncthreads();

    int c4 = lane * 4;
    int r8 = w * 8;

    float4 acc[8];
#pragma unroll
    for (int r = 0; r < 8; r++) acc[r] = make_float4(0.f, 0.f, 0.f, 0.f);

#pragma unroll 4
    for (int k = 0; k < 128; k++) {
        float4 b = *(const float4*)(Bs + k * 128 + c4);
#pragma unroll
        for (int r = 0; r < 8; r++) {
            float a = As[(r8 + r) * 128 + k];
            acc[r].x += a * b.x;
            acc[r].y += a * b.y;
            acc[r].z += a * b.z;
            acc[r].w += a * b.w;
        }
    }

    // epilogue: exp0 -> h_add(ebias) -> log0, write V
    float4 bb = *(const float4*)(ebias + c4);
    float y2 = warp_sum(dot4(bb, bb));
    float4* V4 = (float4*)V;
#pragma unroll
    for (int r = 0; r < 8; r++) {
        float4 u = acc[r];
        float ne2 = warp_sum(dot4(u, u));
        float ne = fmaxf(sqrtf(ne2), EPSF);
        float sc = tanhf(ne) / ne;
        float4 h = make_float4(u.x * sc, u.y * sc, u.z * sc, u.w * sc);
        float xy = warp_sum(dot4(h, bb));
        float x2 = sc * sc * ne2;
        float c1 = 1.f + 2.f * xy + y2;
        float c2 = 1.f - x2;
        float inv_den = 1.f / fmaxf(1.f + 2.f * xy + x2 * y2, EPSF);
        float4 rr = make_float4((c1 * h.x + c2 * bb.x) * inv_den,
                                (c1 * h.y + c2 * bb.y) * inv_den,
                                (c1 * h.z + c2 * bb.z) * inv_den,
                                (c1 * h.w + c2 * bb.w) * inv_den);
        float nr2 = warp_sum(dot4(rr, rr));
        float nr = fmaxf(sqrtf(nr2), EPSF);
        float s = atanhf(fminf(nr, MAX_TANHF)) / nr;
        V4[(size_t)(row0 + r8 + r) * 32 + lane] =
            make_float4(rr.x * s, rr.y * s, rr.z * s, rr.w * s);
    }
}

// ---------------------------------------------------------------------------
// Stage 2: C = log0([x ; exp0(adj @ V)])
// One warp per output row. adj streamed with __ldcs (evict-first: keep V in
// L2) and double-buffered so the stream keeps MLP>=2 across the gather loop.
// ---------------------------------------------------------------------------
__global__ void k_spmm_fused(const float* __restrict__ adj,
                             const float* __restrict__ x, int N) {
    int warp = (blockIdx.x * blockDim.x + threadIdx.x) >> 5;
    int lane = threadIdx.x & 31;
    if (warp >= N) return;

    const float4* V4 = (const float4*)g_V;
    const float4* arow = (const float4*)(adj + (size_t)warp * N);
    float4 acc = make_float4(0.f, 0.f, 0.f, 0.f);

    int nq = N / 4;
    float4 a_cur = __ldcs(arow + lane);
    for (int jb = 0; jb < nq; jb += 32) {
        float4 a_nxt = make_float4(0.f, 0.f, 0.f, 0.f);
        if (jb + 32 < nq) a_nxt = __ldcs(arow + jb + 32 + lane);
#pragma unroll
        for (int c = 0; c < 4; c++) {
            float av = (c == 0) ? a_cur.x : (c == 1) ? a_cur.y
                                : (c == 2) ? a_cur.z : a_cur.w;
            unsigned m = __ballot_sync(0xffffffffu, av != 0.0f);
            while (m) {
                int b = __ffs(m) - 1;
                m &= m - 1;
                float aval = __shfl_sync(0xffffffffu, av, b);
                int j = (jb + b) * 4 + c;
                float4 v = V4[(size_t)j * 32 + lane];
                acc.x += aval * v.x;
                acc.y += aval * v.y;
                acc.z += aval * v.z;
                acc.w += aval * v.w;
            }
        }
        a_cur = a_nxt;
    }

    // epilogue: neigh = exp0(acc); C = log0([x ; neigh])
    float nn2 = warp_sum(dot4(acc, acc));
    float nn = fmaxf(sqrtf(nn2), EPSF);
    float e = tanhf(nn) / nn;
    float4 ng = make_float4(acc.x * e, acc.y * e, acc.z * e, acc.w * e);

    float4 xv = ((const float4*)x)[(size_t)warp * 32 + lane];
    float nx2 = warp_sum(dot4(xv, xv));
    float ng2 = e * e * nn2;
    float nc = fmaxf(sqrtf(nx2 + ng2), EPSF);
    float s = atanhf(fminf(nc, MAX_TANHF)) / nc;

    float4* C4 = (float4*)g_C;
    C4[(size_t)warp * 64 + lane]      = make_float4(xv.x * s, xv.y * s, xv.z * s, xv.w * s);
    C4[(size_t)warp * 64 + 32 + lane] = make_float4(ng.x * s, ng.y * s, ng.z * s, ng.w * s);
}

// ---------------------------------------------------------------------------
// Stage 3: out = h_add( exp0( C @ layer ), lbias )
// ---------------------------------------------------------------------------
__global__ void k_gemm256_fused(const float* __restrict__ A,
                                const float* __restrict__ B,
                                const float* __restrict__ lbias,
                                float* __restrict__ out) {
    extern __shared__ float sm[];
    float* Bs = sm;                // 256*128
    float* As = sm + 256 * 128;    // 64*256
    int tid = threadIdx.x;
    int lane = tid & 31, w = tid >> 5;
    int row0 = blockIdx.x * 64;

    const float4* B4 = (const float4*)B;
    float4* Bs4 = (float4*)Bs;
    for (int i = tid; i < 256 * 128 / 4; i += 256) Bs4[i] = B4[i];

    const float4* A4 = (const float4*)(A + (size_t)row0 * 256);
    float4* As4 = (float4*)As;
    for (int i = tid; i < 64 * 256 / 4; i += 256) As4[i] = A4[i];
    __syncthreads();

    int c4 = lane * 4;
    int r8 = w * 8;

    float4 acc[8];
#pragma unroll
    for (int r = 0; r < 8; r++) acc[r] = make_float4(0.f, 0.f, 0.f, 0.f);

#pragma unroll 4
    for (int k = 0; k < 256; k++) {
        float4 b = *(const float4*)(Bs + k * 128 + c4);
#pragma unroll
        for (int r = 0; r < 8; r++) {
            float a = As[(r8 + r) * 256 + k];
            acc[r].x += a * b.x;
            acc[r].y += a * b.y;
            acc[r].z += a * b.z;
            acc[r].w += a * b.w;
        }
    }

    // epilogue: exp0 -> h_add(lbias), write out
    float4 bb = *(const float4*)(lbias + c4);
    float y2 = warp_sum(dot4(bb, bb));
    float4* O4 = (float4*)out;
#pragma unroll
    for (int r = 0; r < 8; r++) {
        float4 u = acc[r];
        float ne2 = warp_sum(dot4(u, u));
        float ne = fmaxf(sqrtf(ne2), EPSF);
        float sc = tanhf(ne) / ne;
        float4 h = make_float4(u.x * sc, u.y * sc, u.z * sc, u.w * sc);
        float xy = warp_sum(dot4(h, bb));
        float x2 = sc * sc * ne2;
        float c1 = 1.f + 2.f * xy + y2;
        float c2 = 1.f - x2;
        float inv_den = 1.f / fmaxf(1.f + 2.f * xy + x2 * y2, EPSF);
        O4[(size_t)(row0 + r8 + r) * 32 + lane] =
            make_float4((c1 * h.x + c2 * bb.x) * inv_den,
                        (c1 * h.y + c2 * bb.y) * inv_den,
                        (c1 * h.z + c2 * bb.z) * inv_den,
                        (c1 * h.w + c2 * bb.w) * inv_den);
    }
}

// ---------------------------------------------------------------------------
extern "C" void kernel_launch(void* const* d_in, const int* in_sizes, int n_in,
                              void* d_out, int out_size) {
    const float* x     = (const float*)d_in[0];
    const float* adj   = (const float*)d_in[1];
    const float* embed = (const float*)d_in[2];
    const float* layer = (const float*)d_in[3];
    const float* ebias = (const float*)d_in[4];
    const float* lbias = (const float*)d_in[5];
    float* out = (float*)d_out;

    int N = in_sizes[0] / F;  // 8192

    float *pV, *pC;
    cudaGetSymbolAddress((void**)&pV, g_V);
    cudaGetSymbolAddress((void**)&pC, g_C);

    const int SMEM128 = (128 * 128 + 64 * 128) * 4;  //  96 KB
    const int SMEM256 = (256 * 128 + 64 * 256) * 4;  // 192 KB
    cudaFuncSetAttribute(k_gemm128_fused, cudaFuncAttributeMaxDynamicSharedMemorySize, SMEM128);
    cudaFuncSetAttribute(k_gemm256_fused, cudaFuncAttributeMaxDynamicSharedMemorySize, SMEM256);

    k_gemm128_fused<<<N / 64, 256, SMEM128>>>(x, embed, ebias, pV);
    k_spmm_fused<<<N / 8, 256>>>(adj, x, N);
    k_gemm256_fused<<<N / 64, 256, SMEM256>>>(pC, layer, lbias, out);
}